// round 3
// baseline (speedup 1.0000x reference)
#include <cuda_runtime.h>
#include <cstdint>

#define N_NODES 50000
#define HID 128
#define LATENT 64
#define N_GRAPHS 256
#define BN_EPS 1e-5f
#define GEMM_BLOCKS 391          // ceil(50000/128)
#define GATHER_BLOCKS 25000      // 2 nodes per 256-thread block
#define SCAN_BLOCKS 196          // 196*256 = 50176 >= 50000

// ---------------- device scratch (static, no allocation) ----------------
__device__ float g_h0[N_NODES * HID];
__device__ float g_h1[N_NODES * HID];
__device__ float g_tmp[N_NODES * HID];        // hin @ Wr
__device__ float g_agg[N_NODES * HID];        // mean of neighbors
__device__ int   g_deg[N_NODES];
__device__ int   g_rowstart[N_NODES + 1];
__device__ int   g_cursor[N_NODES];
__device__ int   g_csr[800000 * 2];
__device__ int   g_blocksum[SCAN_BLOCKS];
__device__ int   g_blockoff[SCAN_BLOCKS];
__device__ float g_pooled[N_GRAPHS * HID];
__device__ float g_scale[HID];
__device__ float g_shift[HID];

// ---------------- utility ----------------
__global__ void zero_f(float* __restrict__ p, int n) {
    int i = blockIdx.x * blockDim.x + threadIdx.x;
    if (i < n) p[i] = 0.0f;
}
__global__ void zero_i(int* __restrict__ p, int n) {
    int i = blockIdx.x * blockDim.x + threadIdx.x;
    if (i < n) p[i] = 0;
}
__global__ void count_kernel(const int* __restrict__ dst, int nE) {
    int i = blockIdx.x * blockDim.x + threadIdx.x;
    if (i < nE) atomicAdd(&g_deg[dst[i]], 1);
}

// ---------------- parallel 3-phase scan over degrees ----------------
__global__ __launch_bounds__(256) void scan_blocksum() {
    __shared__ int red[256];
    int t = threadIdx.x;
    int i = blockIdx.x * 256 + t;
    int v = (i < N_NODES) ? g_deg[i] : 0;
    red[t] = v;
    __syncthreads();
    for (int off = 128; off > 0; off >>= 1) {
        if (t < off) red[t] += red[t + off];
        __syncthreads();
    }
    if (t == 0) g_blocksum[blockIdx.x] = red[0];
}
__global__ __launch_bounds__(256) void scan_top() {
    __shared__ int s[256];
    int t = threadIdx.x;
    int v = (t < SCAN_BLOCKS) ? g_blocksum[t] : 0;
    s[t] = v;
    __syncthreads();
    for (int off = 1; off < 256; off <<= 1) {
        int u = (t >= off) ? s[t - off] : 0;
        __syncthreads();
        s[t] += u;
        __syncthreads();
    }
    if (t < SCAN_BLOCKS) g_blockoff[t] = s[t] - v;   // exclusive
}
__global__ __launch_bounds__(256) void scan_low(int nE) {
    __shared__ int s[256];
    int t = threadIdx.x;
    int i = blockIdx.x * 256 + t;
    int v = (i < N_NODES) ? g_deg[i] : 0;
    s[t] = v;
    __syncthreads();
    for (int off = 1; off < 256; off <<= 1) {
        int u = (t >= off) ? s[t - off] : 0;
        __syncthreads();
        s[t] += u;
        __syncthreads();
    }
    if (i < N_NODES) {
        int excl = g_blockoff[blockIdx.x] + s[t] - v;
        g_rowstart[i] = excl;
        g_cursor[i] = excl;
        if (i == N_NODES - 1) g_rowstart[N_NODES] = nE;
    }
}

__global__ void fill_kernel(const int* __restrict__ src,
                            const int* __restrict__ dst, int nE) {
    int i = blockIdx.x * blockDim.x + threadIdx.x;
    if (i < nE) {
        int pos = atomicAdd(&g_cursor[dst[i]], 1);
        g_csr[pos] = src[i];
    }
}

// ---------------- packed f32x2 helpers ----------------
__device__ __forceinline__ unsigned long long pack2(float v) {
    unsigned long long r;
    unsigned int u = __float_as_uint(v);
    asm("mov.b64 %0, {%1, %1};" : "=l"(r) : "r"(u));
    return r;
}
__device__ __forceinline__ void ffma2(unsigned long long& acc,
                                      unsigned long long a2,
                                      unsigned long long b2) {
    asm("fma.rn.f32x2 %0, %1, %2, %0;" : "+l"(acc) : "l"(a2), "l"(b2));
}

// ---------------- 128x128x128 GEMM tile (device fn) ----------------
// out[m,n] = A[m,:] @ B (+ add[m,n] + bias[n], relu)  for one 128-row tile.
template <bool RELU_ADD>
__device__ __forceinline__ void gemm128_tile(
    const float* __restrict__ Asrc,
    const float* __restrict__ B,
    const float* __restrict__ addsrc,
    const float* __restrict__ bias,
    float* __restrict__ outp,
    int rowBase)
{
    __shared__ float As[128][33];
    __shared__ float Bs[32][128];

    const int tid = threadIdx.x;
    const int m0 = (tid >> 4) << 3;
    const int n0 = (tid & 15) << 3;

    unsigned long long acc[8][4];
    const unsigned long long z = pack2(0.0f);
#pragma unroll
    for (int i = 0; i < 8; i++)
#pragma unroll
        for (int p = 0; p < 4; p++) acc[i][p] = z;

    for (int kb = 0; kb < 128; kb += 32) {
#pragma unroll
        for (int i = 0; i < 4; i++) {
            int idx = tid + i * 256;            // float4 idx 0..1023
            int kk = idx >> 5;
            int nn = (idx & 31) << 2;
            float4 v = *reinterpret_cast<const float4*>(B + (kb + kk) * 128 + nn);
            *reinterpret_cast<float4*>(&Bs[kk][nn]) = v;
        }
#pragma unroll
        for (int i = 0; i < 4; i++) {
            int idx = tid + i * 256;
            int m = idx >> 3;
            int kq = (idx & 7) << 2;
            int gm = rowBase + m;
            float4 v = make_float4(0.f, 0.f, 0.f, 0.f);
            if (gm < N_NODES)
                v = *reinterpret_cast<const float4*>(Asrc + (size_t)gm * HID + kb + kq);
            As[m][kq + 0] = v.x;
            As[m][kq + 1] = v.y;
            As[m][kq + 2] = v.z;
            As[m][kq + 3] = v.w;
        }
        __syncthreads();

#pragma unroll 4
        for (int k = 0; k < 32; k++) {
            unsigned long long b2[4];
            {
                ulonglong2 t0 = *reinterpret_cast<const ulonglong2*>(&Bs[k][n0]);
                ulonglong2 t1 = *reinterpret_cast<const ulonglong2*>(&Bs[k][n0 + 4]);
                b2[0] = t0.x; b2[1] = t0.y; b2[2] = t1.x; b2[3] = t1.y;
            }
#pragma unroll
            for (int i = 0; i < 8; i++) {
                unsigned long long a2 = pack2(As[m0 + i][k]);
                ffma2(acc[i][0], a2, b2[0]);
                ffma2(acc[i][1], a2, b2[1]);
                ffma2(acc[i][2], a2, b2[2]);
                ffma2(acc[i][3], a2, b2[3]);
            }
        }
        __syncthreads();
    }

#pragma unroll
    for (int i = 0; i < 8; i++) {
        int gm = rowBase + m0 + i;
        if (gm >= N_NODES) break;
#pragma unroll
        for (int p = 0; p < 4; p++) {
            float lo = __uint_as_float((unsigned int)(acc[i][p] & 0xFFFFFFFFull));
            float hi = __uint_as_float((unsigned int)(acc[i][p] >> 32));
            int n = n0 + 2 * p;
            float2 o;
            if (RELU_ADD) {
                float2 t = *reinterpret_cast<const float2*>(addsrc + (size_t)gm * HID + n);
                o.x = fmaxf(lo + t.x + bias[n], 0.0f);
                o.y = fmaxf(hi + t.y + bias[n + 1], 0.0f);
            } else {
                o.x = lo; o.y = hi;
            }
            *reinterpret_cast<float2*>(outp + (size_t)gm * HID + n) = o;
        }
    }
}

// ---------------- fused: tmp = hin@Wr (blocks 0..390)  ||  gather (rest) ----------------
__global__ __launch_bounds__(256) void wr_gather_kernel(
    const float* __restrict__ hin,
    const float* __restrict__ Wr)
{
    if (blockIdx.x < GEMM_BLOCKS) {
        gemm128_tile<false>(hin, Wr, nullptr, nullptr, g_tmp, blockIdx.x * 128);
        return;
    }
    // gather: 2 nodes per block, 128 threads each
    int node = (blockIdx.x - GEMM_BLOCKS) * 2 + (threadIdx.x >> 7);
    if (node >= N_NODES) return;
    int c = threadIdx.x & 127;
    int s0 = g_rowstart[node];
    int s1 = g_rowstart[node + 1];
    float acc = 0.0f;
    int j = s0;
    for (; j + 4 <= s1; j += 4) {
        int i0 = __ldg(&g_csr[j + 0]);
        int i1 = __ldg(&g_csr[j + 1]);
        int i2 = __ldg(&g_csr[j + 2]);
        int i3 = __ldg(&g_csr[j + 3]);
        float a = hin[(size_t)i0 * HID + c];
        float b = hin[(size_t)i1 * HID + c];
        float d = hin[(size_t)i2 * HID + c];
        float e = hin[(size_t)i3 * HID + c];
        acc += (a + b) + (d + e);
    }
    for (; j < s1; j++)
        acc += hin[(size_t)__ldg(&g_csr[j]) * HID + c];
    int deg = s1 - s0;
    float inv = 1.0f / (float)(deg > 0 ? deg : 1);
    g_agg[(size_t)node * HID + c] = acc * inv;
}

// ---------------- hout = relu(agg@Wl + tmp + bl) ----------------
__global__ __launch_bounds__(256) void wl_kernel(
    const float* __restrict__ Wl,
    const float* __restrict__ bl,
    float* __restrict__ hout)
{
    gemm128_tile<true>(g_agg, Wl, g_tmp, bl, hout, blockIdx.x * 128);
}

// ---------------- pooled = segment_sum(h, batch) (batch sorted) ----------------
__global__ __launch_bounds__(128) void pool_kernel(
    const float* __restrict__ hin, const int* __restrict__ batch)
{
    int base = blockIdx.x * 128;
    int c = threadIdx.x;
    int limit = N_NODES - base;
    if (limit > 128) limit = 128;
    if (limit <= 0) return;
    int cur = __ldg(&batch[base]);
    float acc = 0.0f;
    for (int r = 0; r < limit; r++) {
        int b = __ldg(&batch[base + r]);
        if (b != cur) {
            atomicAdd(&g_pooled[cur * HID + c], acc);
            acc = 0.0f;
            cur = b;
        }
        acc += hin[(size_t)(base + r) * HID + c];
    }
    atomicAdd(&g_pooled[cur * HID + c], acc);
}

// ---------------- batchnorm stats ----------------
__global__ __launch_bounds__(128) void bn_kernel(
    const float* __restrict__ gamma, const float* __restrict__ beta)
{
    int c = threadIdx.x;
    float s = 0.0f, s2 = 0.0f;
    for (int g = 0; g < N_GRAPHS; g++) {
        float v = g_pooled[g * HID + c];
        s += v;
        s2 += v * v;
    }
    float mu = s * (1.0f / N_GRAPHS);
    float var = s2 * (1.0f / N_GRAPHS) - mu * mu;
    float sc = gamma[c] * rsqrtf(var + BN_EPS);
    g_scale[c] = sc;
    g_shift[c] = beta[c] - mu * sc;
}

// ---------------- final FC ----------------
__global__ __launch_bounds__(64) void final_kernel(
    const float* __restrict__ fcW, const float* __restrict__ fcb,
    float* __restrict__ out)
{
    __shared__ float row[HID];
    int g = blockIdx.x;
    int l = threadIdx.x;
    for (int c = l; c < HID; c += 64)
        row[c] = g_pooled[g * HID + c] * g_scale[c] + g_shift[c];
    __syncthreads();
    float acc = fcb[l];
#pragma unroll
    for (int c = 0; c < HID; c++)
        acc += row[c] * __ldg(&fcW[c * LATENT + l]);
    out[g * LATENT + l] = acc;
}

// ---------------- launch ----------------
extern "C" void kernel_launch(void* const* d_in, const int* in_sizes, int n_in,
                              void* d_out, int out_size)
{
    const float* x     = (const float*)d_in[0];
    const int*   ei    = (const int*)d_in[1];
    const int*   batch = (const int*)d_in[2];
    const float* Wl    = (const float*)d_in[3];
    const float* bl    = (const float*)d_in[4];
    const float* Wr    = (const float*)d_in[5];
    const float* gamma = (const float*)d_in[6];
    const float* beta  = (const float*)d_in[7];
    const float* fcW   = (const float*)d_in[8];
    const float* fcb   = (const float*)d_in[9];
    float* out = (float*)d_out;

    const int E = in_sizes[1] / 2;
    const int* src = ei;
    const int* dst = ei + E;

    float *h0, *h1, *pooled;
    int *deg;
    cudaGetSymbolAddress((void**)&h0, g_h0);
    cudaGetSymbolAddress((void**)&h1, g_h1);
    cudaGetSymbolAddress((void**)&pooled, g_pooled);
    cudaGetSymbolAddress((void**)&deg, g_deg);

    // ---- CSR build ----
    zero_i<<<(N_NODES + 255) / 256, 256>>>(deg, N_NODES);
    zero_f<<<(N_GRAPHS * HID + 255) / 256, 256>>>(pooled, N_GRAPHS * HID);
    count_kernel<<<(E + 255) / 256, 256>>>(dst, E);
    scan_blocksum<<<SCAN_BLOCKS, 256>>>();
    scan_top<<<1, 256>>>();
    scan_low<<<SCAN_BLOCKS, 256>>>(E);
    fill_kernel<<<(E + 255) / 256, 256>>>(src, dst, E);

    const float* hin = x;
    float* houts[3] = { h0, h1, h0 };
    for (int layer = 0; layer < 3; layer++) {
        wr_gather_kernel<<<GEMM_BLOCKS + GATHER_BLOCKS, 256>>>(
            hin, Wr + layer * HID * HID);
        wl_kernel<<<GEMM_BLOCKS, 256>>>(
            Wl + layer * HID * HID, bl + layer * HID, houts[layer]);
        hin = houts[layer];
    }

    pool_kernel<<<(N_NODES + 127) / 128, 128>>>(h0, batch);
    bn_kernel<<<1, 128>>>(gamma, beta);
    final_kernel<<<N_GRAPHS, 64>>>(fcW, fcb, out);
}

// round 4
// speedup vs baseline: 2.3408x; 2.3408x over previous
#include <cuda_runtime.h>
#include <cstdint>

#define N_NODES 50000
#define HID 128
#define LATENT 64
#define N_GRAPHS 256
#define BN_EPS 1e-5f
#define SCAN_BLOCKS 196          // 196*256 >= 50000
#define GEMM_BLOCKS 391          // ceil(50000/128)

// dynamic smem partition for the MMA GEMM
#define AS_PAD 36                // conflict-free A frag loads
#define BS_PAD 136               // conflict-free B frag loads
#define SMEM_AS_BYTES (128 * AS_PAD * 4)
#define SMEM_BS_ELEMS (32 * BS_PAD)
#define SMEM_TOTAL_BYTES (SMEM_AS_BYTES + 2 * SMEM_BS_ELEMS * 4)

// ---------------- device scratch (static, no allocation) ----------------
__device__ float g_h0[N_NODES * HID];
__device__ float g_h1[N_NODES * HID];
__device__ float g_agg[N_NODES * HID];        // mean of neighbors
__device__ int   g_deg[N_NODES];
__device__ int   g_rowstart[N_NODES + 1];
__device__ int   g_cursor[N_NODES];
__device__ int   g_csr[800000 * 2];
__device__ int   g_blocksum[SCAN_BLOCKS];
__device__ int   g_blockoff[SCAN_BLOCKS];
__device__ float g_pooled[N_GRAPHS * HID];
__device__ float g_scale[HID];
__device__ float g_shift[HID];
__device__ unsigned int g_Bhi[3 * 256 * 128]; // per-layer fused [Wl;Wr] tf32-hi
__device__ unsigned int g_Blo[3 * 256 * 128]; // tf32-lo residual

// ---------------- utility ----------------
__global__ void zero_f(float* __restrict__ p, int n) {
    int i = blockIdx.x * blockDim.x + threadIdx.x;
    if (i < n) p[i] = 0.0f;
}
__global__ void zero_i(int* __restrict__ p, int n) {
    int i = blockIdx.x * blockDim.x + threadIdx.x;
    if (i < n) p[i] = 0;
}
__global__ void count_kernel(const int* __restrict__ dst, int nE) {
    int i = blockIdx.x * blockDim.x + threadIdx.x;
    if (i < nE) atomicAdd(&g_deg[dst[i]], 1);
}

// ---------------- parallel 3-phase scan over degrees ----------------
__global__ __launch_bounds__(256) void scan_blocksum() {
    __shared__ int red[256];
    int t = threadIdx.x;
    int i = blockIdx.x * 256 + t;
    int v = (i < N_NODES) ? g_deg[i] : 0;
    red[t] = v;
    __syncthreads();
    for (int off = 128; off > 0; off >>= 1) {
        if (t < off) red[t] += red[t + off];
        __syncthreads();
    }
    if (t == 0) g_blocksum[blockIdx.x] = red[0];
}
__global__ __launch_bounds__(256) void scan_top() {
    __shared__ int s[256];
    int t = threadIdx.x;
    int v = (t < SCAN_BLOCKS) ? g_blocksum[t] : 0;
    s[t] = v;
    __syncthreads();
    for (int off = 1; off < 256; off <<= 1) {
        int u = (t >= off) ? s[t - off] : 0;
        __syncthreads();
        s[t] += u;
        __syncthreads();
    }
    if (t < SCAN_BLOCKS) g_blockoff[t] = s[t] - v;   // exclusive
}
__global__ __launch_bounds__(256) void scan_low(int nE) {
    __shared__ int s[256];
    int t = threadIdx.x;
    int i = blockIdx.x * 256 + t;
    int v = (i < N_NODES) ? g_deg[i] : 0;
    s[t] = v;
    __syncthreads();
    for (int off = 1; off < 256; off <<= 1) {
        int u = (t >= off) ? s[t - off] : 0;
        __syncthreads();
        s[t] += u;
        __syncthreads();
    }
    if (i < N_NODES) {
        int excl = g_blockoff[blockIdx.x] + s[t] - v;
        g_rowstart[i] = excl;
        g_cursor[i] = excl;
        if (i == N_NODES - 1) g_rowstart[N_NODES] = nE;
    }
}

__global__ void fill_kernel(const int* __restrict__ src,
                            const int* __restrict__ dst, int nE) {
    int i = blockIdx.x * blockDim.x + threadIdx.x;
    if (i < nE) {
        int pos = atomicAdd(&g_cursor[dst[i]], 1);
        g_csr[pos] = src[i];
    }
}

// ---------------- weight split: fused B[L][k][n] -> tf32 hi/lo ----------------
__global__ void bsplit_kernel(const float* __restrict__ Wl,
                              const float* __restrict__ Wr) {
    int i = blockIdx.x * blockDim.x + threadIdx.x;
    if (i >= 3 * 256 * 128) return;
    int L = i >> 15;          // / 32768
    int r = i & 32767;
    int k = r >> 7;
    int n = r & 127;
    float v = (k < 128) ? Wl[L * 16384 + k * 128 + n]
                        : Wr[L * 16384 + (k - 128) * 128 + n];
    unsigned int hi;
    asm("cvt.rna.tf32.f32 %0, %1;" : "=r"(hi) : "f"(v));
    float lof = v - __uint_as_float(hi);
    unsigned int lo;
    asm("cvt.rna.tf32.f32 %0, %1;" : "=r"(lo) : "f"(lof));
    g_Bhi[i] = hi;
    g_Blo[i] = lo;
}

// ---------------- gather: mean over incoming neighbors ----------------
__global__ __launch_bounds__(128) void gather_kernel(const float* __restrict__ hin) {
    int node = blockIdx.x;
    int c = threadIdx.x;
    int s0 = g_rowstart[node];
    int s1 = g_rowstart[node + 1];
    float acc = 0.0f;
    int j = s0;
    for (; j + 4 <= s1; j += 4) {
        int i0 = __ldg(&g_csr[j + 0]);
        int i1 = __ldg(&g_csr[j + 1]);
        int i2 = __ldg(&g_csr[j + 2]);
        int i3 = __ldg(&g_csr[j + 3]);
        float a = hin[(size_t)i0 * HID + c];
        float b = hin[(size_t)i1 * HID + c];
        float d = hin[(size_t)i2 * HID + c];
        float e = hin[(size_t)i3 * HID + c];
        acc += (a + b) + (d + e);
    }
    for (; j < s1; j++)
        acc += hin[(size_t)__ldg(&g_csr[j]) * HID + c];
    int deg = s1 - s0;
    float inv = 1.0f / (float)(deg > 0 ? deg : 1);
    g_agg[(size_t)node * HID + c] = acc * inv;
}

// ---------------- tf32 MMA GEMM ----------------
// hout[m,n] = relu( [agg|hin][m,:] @ [Bhi+Blo] + bl[n] ),  K=256
// block 128x128, 8 warps (4m x 2n), warp tile 32x64, 2-term tf32 split.
__device__ __forceinline__ void tf32split(float v, unsigned int& hi, unsigned int& lo) {
    asm("cvt.rna.tf32.f32 %0, %1;" : "=r"(hi) : "f"(v));
    float l = v - __uint_as_float(hi);
    asm("cvt.rna.tf32.f32 %0, %1;" : "=r"(lo) : "f"(l));
}

#define MMA_TF32(d, a0, a1, a2, a3, b0, b1)                                \
    asm volatile("mma.sync.aligned.m16n8k8.row.col.f32.tf32.tf32.f32 "     \
                 "{%0,%1,%2,%3}, {%4,%5,%6,%7}, {%8,%9}, {%0,%1,%2,%3};"   \
                 : "+f"(d[0]), "+f"(d[1]), "+f"(d[2]), "+f"(d[3])          \
                 : "r"(a0), "r"(a1), "r"(a2), "r"(a3), "r"(b0), "r"(b1))

__global__ __launch_bounds__(256) void sage_mma_kernel(
    const float* __restrict__ hin,
    const unsigned int* __restrict__ Bhi,   // [256][128] this layer
    const unsigned int* __restrict__ Blo,
    const float* __restrict__ bl,
    float* __restrict__ hout)
{
    extern __shared__ unsigned char dynsmem[];
    float* As = (float*)dynsmem;                                  // [128][AS_PAD]
    unsigned int* BsHi = (unsigned int*)(dynsmem + SMEM_AS_BYTES); // [32][BS_PAD]
    unsigned int* BsLo = BsHi + SMEM_BS_ELEMS;

    const int tid = threadIdx.x;
    const int lane = tid & 31;
    const int wid = tid >> 5;
    const int m0w = (wid >> 1) * 32;
    const int n0w = (wid & 1) * 64;
    const int rowBase = blockIdx.x * 128;
    const int grp = lane >> 2;   // 0..7
    const int tig = lane & 3;    // 0..3

    float acc[2][8][4];
#pragma unroll
    for (int mt = 0; mt < 2; mt++)
#pragma unroll
        for (int nt = 0; nt < 8; nt++)
#pragma unroll
            for (int q = 0; q < 4; q++) acc[mt][nt][q] = 0.0f;

    for (int kb = 0; kb < 256; kb += 32) {
        // --- B chunk (hi+lo), coalesced uint4 ---
#pragma unroll
        for (int i = 0; i < 4; i++) {
            int idx = tid + i * 256;            // 0..1023 vec4 units
            int kk = idx >> 5;                  // 0..31
            int nn = (idx & 31) << 2;           // 0..124
            uint4 vh = *reinterpret_cast<const uint4*>(Bhi + (kb + kk) * 128 + nn);
            *reinterpret_cast<uint4*>(&BsHi[kk * BS_PAD + nn]) = vh;
            uint4 vl = *reinterpret_cast<const uint4*>(Blo + (kb + kk) * 128 + nn);
            *reinterpret_cast<uint4*>(&BsLo[kk * BS_PAD + nn]) = vl;
        }
        // --- A chunk: agg for kb<128, hin after ---
        const float* Asrc = (kb < 128) ? (g_agg + kb) : (hin + (kb - 128));
#pragma unroll
        for (int i = 0; i < 4; i++) {
            int idx = tid + i * 256;
            int m = idx >> 3;
            int kq = (idx & 7) << 2;
            int gm = rowBase + m;
            float4 v = make_float4(0.f, 0.f, 0.f, 0.f);
            if (gm < N_NODES)
                v = *reinterpret_cast<const float4*>(Asrc + (size_t)gm * HID + kq);
            *reinterpret_cast<float4*>(&As[m * AS_PAD + kq]) = v;
        }
        __syncthreads();

#pragma unroll
        for (int ks = 0; ks < 4; ks++) {
            const int k0 = ks * 8;
            // A fragments (2 m-tiles), conflict-free (bank = 4*grp+tig)
            unsigned int ahi[2][4], alo[2][4];
#pragma unroll
            for (int mt = 0; mt < 2; mt++) {
                int mr = m0w + mt * 16 + grp;
                float a0 = As[mr * AS_PAD + k0 + tig];
                float a1 = As[(mr + 8) * AS_PAD + k0 + tig];
                float a2 = As[mr * AS_PAD + k0 + tig + 4];
                float a3 = As[(mr + 8) * AS_PAD + k0 + tig + 4];
                tf32split(a0, ahi[mt][0], alo[mt][0]);
                tf32split(a1, ahi[mt][1], alo[mt][1]);
                tf32split(a2, ahi[mt][2], alo[mt][2]);
                tf32split(a3, ahi[mt][3], alo[mt][3]);
            }
#pragma unroll
            for (int nt = 0; nt < 8; nt++) {
                int n = n0w + nt * 8 + grp;
                // B fragments, conflict-free (bank = 8*tig+grp)
                unsigned int bh0 = BsHi[(k0 + tig) * BS_PAD + n];
                unsigned int bh1 = BsHi[(k0 + tig + 4) * BS_PAD + n];
                unsigned int bl0 = BsLo[(k0 + tig) * BS_PAD + n];
                unsigned int bl1 = BsLo[(k0 + tig + 4) * BS_PAD + n];
#pragma unroll
                for (int mt = 0; mt < 2; mt++) {
                    MMA_TF32(acc[mt][nt], ahi[mt][0], ahi[mt][1], ahi[mt][2], ahi[mt][3], bh0, bh1);
                    MMA_TF32(acc[mt][nt], alo[mt][0], alo[mt][1], alo[mt][2], alo[mt][3], bh0, bh1);
                    MMA_TF32(acc[mt][nt], ahi[mt][0], ahi[mt][1], ahi[mt][2], ahi[mt][3], bl0, bl1);
                }
            }
        }
        __syncthreads();
    }

    // --- epilogue: +bias, relu, float2 stores ---
#pragma unroll
    for (int mt = 0; mt < 2; mt++) {
        int gm0 = rowBase + m0w + mt * 16 + grp;
        int gm1 = gm0 + 8;
#pragma unroll
        for (int nt = 0; nt < 8; nt++) {
            int n = n0w + nt * 8 + 2 * tig;
            float2 bb = *reinterpret_cast<const float2*>(bl + n);
            if (gm0 < N_NODES) {
                float2 o;
                o.x = fmaxf(acc[mt][nt][0] + bb.x, 0.0f);
                o.y = fmaxf(acc[mt][nt][1] + bb.y, 0.0f);
                *reinterpret_cast<float2*>(hout + (size_t)gm0 * HID + n) = o;
            }
            if (gm1 < N_NODES) {
                float2 o;
                o.x = fmaxf(acc[mt][nt][2] + bb.x, 0.0f);
                o.y = fmaxf(acc[mt][nt][3] + bb.y, 0.0f);
                *reinterpret_cast<float2*>(hout + (size_t)gm1 * HID + n) = o;
            }
        }
    }
}

// ---------------- pooled = segment_sum(h, batch) (batch sorted) ----------------
__global__ __launch_bounds__(128) void pool_kernel(
    const float* __restrict__ hin, const int* __restrict__ batch)
{
    int base = blockIdx.x * 128;
    int c = threadIdx.x;
    int limit = N_NODES - base;
    if (limit > 128) limit = 128;
    if (limit <= 0) return;
    int cur = __ldg(&batch[base]);
    float acc = 0.0f;
    for (int r = 0; r < limit; r++) {
        int b = __ldg(&batch[base + r]);
        if (b != cur) {
            atomicAdd(&g_pooled[cur * HID + c], acc);
            acc = 0.0f;
            cur = b;
        }
        acc += hin[(size_t)(base + r) * HID + c];
    }
    atomicAdd(&g_pooled[cur * HID + c], acc);
}

// ---------------- batchnorm stats ----------------
__global__ __launch_bounds__(128) void bn_kernel(
    const float* __restrict__ gamma, const float* __restrict__ beta)
{
    int c = threadIdx.x;
    float s = 0.0f, s2 = 0.0f;
    for (int g = 0; g < N_GRAPHS; g++) {
        float v = g_pooled[g * HID + c];
        s += v;
        s2 += v * v;
    }
    float mu = s * (1.0f / N_GRAPHS);
    float var = s2 * (1.0f / N_GRAPHS) - mu * mu;
    float sc = gamma[c] * rsqrtf(var + BN_EPS);
    g_scale[c] = sc;
    g_shift[c] = beta[c] - mu * sc;
}

// ---------------- final FC ----------------
__global__ __launch_bounds__(64) void final_kernel(
    const float* __restrict__ fcW, const float* __restrict__ fcb,
    float* __restrict__ out)
{
    __shared__ float row[HID];
    int g = blockIdx.x;
    int l = threadIdx.x;
    for (int c = l; c < HID; c += 64)
        row[c] = g_pooled[g * HID + c] * g_scale[c] + g_shift[c];
    __syncthreads();
    float acc = fcb[l];
#pragma unroll
    for (int c = 0; c < HID; c++)
        acc += row[c] * __ldg(&fcW[c * LATENT + l]);
    out[g * LATENT + l] = acc;
}

// ---------------- launch ----------------
extern "C" void kernel_launch(void* const* d_in, const int* in_sizes, int n_in,
                              void* d_out, int out_size)
{
    const float* x     = (const float*)d_in[0];
    const int*   ei    = (const int*)d_in[1];
    const int*   batch = (const int*)d_in[2];
    const float* Wl    = (const float*)d_in[3];
    const float* bl    = (const float*)d_in[4];
    const float* Wr    = (const float*)d_in[5];
    const float* gamma = (const float*)d_in[6];
    const float* beta  = (const float*)d_in[7];
    const float* fcW   = (const float*)d_in[8];
    const float* fcb   = (const float*)d_in[9];
    float* out = (float*)d_out;

    const int E = in_sizes[1] / 2;
    const int* src = ei;
    const int* dst = ei + E;

    float *h0, *h1, *pooled;
    int *deg;
    unsigned int *bhi, *blo;
    cudaGetSymbolAddress((void**)&h0, g_h0);
    cudaGetSymbolAddress((void**)&h1, g_h1);
    cudaGetSymbolAddress((void**)&pooled, g_pooled);
    cudaGetSymbolAddress((void**)&deg, g_deg);
    cudaGetSymbolAddress((void**)&bhi, g_Bhi);
    cudaGetSymbolAddress((void**)&blo, g_Blo);

    cudaFuncSetAttribute(sage_mma_kernel,
                         cudaFuncAttributeMaxDynamicSharedMemorySize,
                         SMEM_TOTAL_BYTES);

    // ---- CSR build + weight split ----
    zero_i<<<(N_NODES + 255) / 256, 256>>>(deg, N_NODES);
    zero_f<<<(N_GRAPHS * HID + 255) / 256, 256>>>(pooled, N_GRAPHS * HID);
    count_kernel<<<(E + 255) / 256, 256>>>(dst, E);
    scan_blocksum<<<SCAN_BLOCKS, 256>>>();
    scan_top<<<1, 256>>>();
    scan_low<<<SCAN_BLOCKS, 256>>>(E);
    fill_kernel<<<(E + 255) / 256, 256>>>(src, dst, E);
    bsplit_kernel<<<(3 * 256 * 128 + 255) / 256, 256>>>(Wl, Wr);

    const float* hin = x;
    float* houts[3] = { h0, h1, h0 };
    for (int layer = 0; layer < 3; layer++) {
        gather_kernel<<<N_NODES, 128>>>(hin);
        sage_mma_kernel<<<GEMM_BLOCKS, 256, SMEM_TOTAL_BYTES>>>(
            hin, bhi + layer * 256 * 128, blo + layer * 256 * 128,
            bl + layer * HID, houts[layer]);
        hin = houts[layer];
    }

    pool_kernel<<<(N_NODES + 127) / 128, 128>>>(h0, batch);
    bn_kernel<<<1, 128>>>(gamma, beta);
    final_kernel<<<N_GRAPHS, 64>>>(fcW, fcb, out);
}

// round 5
// speedup vs baseline: 2.7710x; 1.1838x over previous
#include <cuda_runtime.h>
#include <cstdint>

#define N_NODES 50000
#define HID 128
#define LATENT 64
#define N_GRAPHS 256
#define BN_EPS 1e-5f
#define SCAN_BLOCKS 196          // 196*256 >= 50000
#define GEMM_BLOCKS 391          // ceil(50000/128)

// dynamic smem partition for the MMA GEMM
#define AS_PAD 36                // conflict-free A frag loads (float2: 18*grp+tig distinct)
#define BS_PAD 136               // conflict-free B frag loads (8*tig+grp distinct)
#define SMEM_AS_BYTES (128 * AS_PAD * 4)
#define SMEM_BS_ELEMS (16 * BS_PAD)      // 16 k2-rows of bf16x2 per 32-k chunk
#define SMEM_TOTAL_BYTES (SMEM_AS_BYTES + 2 * SMEM_BS_ELEMS * 4)

// ---------------- device scratch (static, no allocation) ----------------
__device__ float g_h0[N_NODES * HID];
__device__ float g_h1[N_NODES * HID];
__device__ float g_agg[N_NODES * HID];        // mean of neighbors
__device__ int   g_deg[N_NODES];
__device__ int   g_rowstart[N_NODES + 1];
__device__ int   g_cursor[N_NODES];
__device__ int   g_csr[800000 * 2];
__device__ int   g_blocksum[SCAN_BLOCKS];
__device__ int   g_blockoff[SCAN_BLOCKS];
__device__ float g_pooled[N_GRAPHS * HID];
__device__ float g_scale[HID];
__device__ float g_shift[HID];
__device__ unsigned int g_Bhi[3 * 128 * 128]; // per-layer fused [Wl;Wr], bf16x2 packed along k
__device__ unsigned int g_Blo[3 * 128 * 128]; // bf16 residual, packed

// ---------------- utility ----------------
__global__ void zero_f(float* __restrict__ p, int n) {
    int i = blockIdx.x * blockDim.x + threadIdx.x;
    if (i < n) p[i] = 0.0f;
}
__global__ void zero_i(int* __restrict__ p, int n) {
    int i = blockIdx.x * blockDim.x + threadIdx.x;
    if (i < n) p[i] = 0;
}
__global__ void count_kernel(const int* __restrict__ dst, int nE) {
    int i = blockIdx.x * blockDim.x + threadIdx.x;
    if (i < nE) atomicAdd(&g_deg[dst[i]], 1);
}

// ---------------- parallel 3-phase scan over degrees ----------------
__global__ __launch_bounds__(256) void scan_blocksum() {
    __shared__ int red[256];
    int t = threadIdx.x;
    int i = blockIdx.x * 256 + t;
    int v = (i < N_NODES) ? g_deg[i] : 0;
    red[t] = v;
    __syncthreads();
    for (int off = 128; off > 0; off >>= 1) {
        if (t < off) red[t] += red[t + off];
        __syncthreads();
    }
    if (t == 0) g_blocksum[blockIdx.x] = red[0];
}
__global__ __launch_bounds__(256) void scan_top() {
    __shared__ int s[256];
    int t = threadIdx.x;
    int v = (t < SCAN_BLOCKS) ? g_blocksum[t] : 0;
    s[t] = v;
    __syncthreads();
    for (int off = 1; off < 256; off <<= 1) {
        int u = (t >= off) ? s[t - off] : 0;
        __syncthreads();
        s[t] += u;
        __syncthreads();
    }
    if (t < SCAN_BLOCKS) g_blockoff[t] = s[t] - v;   // exclusive
}
__global__ __launch_bounds__(256) void scan_low(int nE) {
    __shared__ int s[256];
    int t = threadIdx.x;
    int i = blockIdx.x * 256 + t;
    int v = (i < N_NODES) ? g_deg[i] : 0;
    s[t] = v;
    __syncthreads();
    for (int off = 1; off < 256; off <<= 1) {
        int u = (t >= off) ? s[t - off] : 0;
        __syncthreads();
        s[t] += u;
        __syncthreads();
    }
    if (i < N_NODES) {
        int excl = g_blockoff[blockIdx.x] + s[t] - v;
        g_rowstart[i] = excl;
        g_cursor[i] = excl;
        if (i == N_NODES - 1) g_rowstart[N_NODES] = nE;
    }
}

__global__ void fill_kernel(const int* __restrict__ src,
                            const int* __restrict__ dst, int nE) {
    int i = blockIdx.x * blockDim.x + threadIdx.x;
    if (i < nE) {
        int pos = atomicAdd(&g_cursor[dst[i]], 1);
        g_csr[pos] = src[i];
    }
}

// ---------------- weight split: fused B[L][k][n] -> packed bf16x2 hi/lo ----------------
// g_Bhi[L][k2][n] holds (B[2*k2][n], B[2*k2+1][n]) as bf16x2 (low = even k).
__global__ void bsplit_kernel(const float* __restrict__ Wl,
                              const float* __restrict__ Wr) {
    int i = blockIdx.x * blockDim.x + threadIdx.x;
    if (i >= 3 * 128 * 128) return;
    int L = i >> 14;          // / 16384
    int r = i & 16383;
    int k2 = r >> 7;
    int n = r & 127;
    int k = k2 << 1;          // even, so k and k+1 are in the same matrix
    const float* W = (k < 128) ? (Wl + L * 16384 + k * 128)
                               : (Wr + L * 16384 + (k - 128) * 128);
    float f0 = W[n];
    float f1 = W[128 + n];
    unsigned int hi;
    asm("cvt.rn.bf16x2.f32 %0, %1, %2;" : "=r"(hi) : "f"(f1), "f"(f0));
    float h0 = __uint_as_float(hi << 16);
    float h1 = __uint_as_float(hi & 0xFFFF0000u);
    unsigned int lo;
    asm("cvt.rn.bf16x2.f32 %0, %1, %2;" : "=r"(lo) : "f"(f1 - h1), "f"(f0 - h0));
    g_Bhi[i] = hi;
    g_Blo[i] = lo;
}

// ---------------- gather: mean over incoming neighbors ----------------
__global__ __launch_bounds__(128) void gather_kernel(const float* __restrict__ hin) {
    int node = blockIdx.x;
    int c = threadIdx.x;
    int s0 = g_rowstart[node];
    int s1 = g_rowstart[node + 1];
    float acc = 0.0f;
    int j = s0;
    for (; j + 4 <= s1; j += 4) {
        int i0 = __ldg(&g_csr[j + 0]);
        int i1 = __ldg(&g_csr[j + 1]);
        int i2 = __ldg(&g_csr[j + 2]);
        int i3 = __ldg(&g_csr[j + 3]);
        float a = hin[(size_t)i0 * HID + c];
        float b = hin[(size_t)i1 * HID + c];
        float d = hin[(size_t)i2 * HID + c];
        float e = hin[(size_t)i3 * HID + c];
        acc += (a + b) + (d + e);
    }
    for (; j < s1; j++)
        acc += hin[(size_t)__ldg(&g_csr[j]) * HID + c];
    int deg = s1 - s0;
    float inv = 1.0f / (float)(deg > 0 ? deg : 1);
    g_agg[(size_t)node * HID + c] = acc * inv;
}

// ---------------- bf16 3-pass MMA GEMM ----------------
// hout[m,n] = relu( [agg|hin][m,:] @ (Bhi+Blo) + bl[n] ),  K=256
// block 128x128, 8 warps (4m x 2n), warp tile 32x64, mma m16n8k16 bf16.
__device__ __forceinline__ void bf16split2(float2 f, unsigned int& hi, unsigned int& lo) {
    asm("cvt.rn.bf16x2.f32 %0, %1, %2;" : "=r"(hi) : "f"(f.y), "f"(f.x));
    float hx = __uint_as_float(hi << 16);
    float hy = __uint_as_float(hi & 0xFFFF0000u);
    asm("cvt.rn.bf16x2.f32 %0, %1, %2;" : "=r"(lo) : "f"(f.y - hy), "f"(f.x - hx));
}

#define MMA_BF16(d, a0, a1, a2, a3, b0, b1)                                 \
    asm volatile("mma.sync.aligned.m16n8k16.row.col.f32.bf16.bf16.f32 "     \
                 "{%0,%1,%2,%3}, {%4,%5,%6,%7}, {%8,%9}, {%0,%1,%2,%3};"    \
                 : "+f"(d[0]), "+f"(d[1]), "+f"(d[2]), "+f"(d[3])           \
                 : "r"(a0), "r"(a1), "r"(a2), "r"(a3), "r"(b0), "r"(b1))

__global__ __launch_bounds__(256) void sage_mma_kernel(
    const float* __restrict__ hin,
    const unsigned int* __restrict__ Bhi,   // [128 k2][128 n] this layer
    const unsigned int* __restrict__ Blo,
    const float* __restrict__ bl,
    float* __restrict__ hout)
{
    extern __shared__ unsigned char dynsmem[];
    float* As = (float*)dynsmem;                                   // [128][AS_PAD]
    unsigned int* BsHi = (unsigned int*)(dynsmem + SMEM_AS_BYTES); // [16][BS_PAD]
    unsigned int* BsLo = BsHi + SMEM_BS_ELEMS;

    const int tid = threadIdx.x;
    const int lane = tid & 31;
    const int wid = tid >> 5;
    const int m0w = (wid >> 1) * 32;
    const int n0w = (wid & 1) * 64;
    const int rowBase = blockIdx.x * 128;
    const int grp = lane >> 2;   // 0..7
    const int tig = lane & 3;    // 0..3

    float acc[2][8][4];
#pragma unroll
    for (int mt = 0; mt < 2; mt++)
#pragma unroll
        for (int nt = 0; nt < 8; nt++)
#pragma unroll
            for (int q = 0; q < 4; q++) acc[mt][nt][q] = 0.0f;

    for (int kb = 0; kb < 256; kb += 32) {
        // --- B chunk: 16 k2-rows x 128 n, hi+lo, coalesced uint4 ---
#pragma unroll
        for (int i = 0; i < 2; i++) {
            int idx = tid + i * 256;            // 0..511 uint4 units
            int kk2 = idx >> 5;                 // 0..15
            int nn = (idx & 31) << 2;           // 0..124
            uint4 vh = *reinterpret_cast<const uint4*>(Bhi + ((kb >> 1) + kk2) * 128 + nn);
            *reinterpret_cast<uint4*>(&BsHi[kk2 * BS_PAD + nn]) = vh;
            uint4 vl = *reinterpret_cast<const uint4*>(Blo + ((kb >> 1) + kk2) * 128 + nn);
            *reinterpret_cast<uint4*>(&BsLo[kk2 * BS_PAD + nn]) = vl;
        }
        // --- A chunk: agg for kb<128, hin after ---
        const float* Asrc = (kb < 128) ? (g_agg + kb) : (hin + (kb - 128));
#pragma unroll
        for (int i = 0; i < 4; i++) {
            int idx = tid + i * 256;
            int m = idx >> 3;
            int kq = (idx & 7) << 2;
            int gm = rowBase + m;
            float4 v = make_float4(0.f, 0.f, 0.f, 0.f);
            if (gm < N_NODES)
                v = *reinterpret_cast<const float4*>(Asrc + (size_t)gm * HID + kq);
            *reinterpret_cast<float4*>(&As[m * AS_PAD + kq]) = v;
        }
        __syncthreads();

#pragma unroll
        for (int ks = 0; ks < 2; ks++) {
            const int k0 = ks * 16;       // k offset in chunk
            const int k2b = ks * 8;       // k2 offset in chunk
            // A fragments (2 m-tiles), float2 LDS conflict-free
            unsigned int ahi[2][4], alo[2][4];
#pragma unroll
            for (int mt = 0; mt < 2; mt++) {
                int mr = m0w + mt * 16 + grp;
                float2 f0 = *reinterpret_cast<const float2*>(&As[mr * AS_PAD + k0 + 2 * tig]);
                float2 f1 = *reinterpret_cast<const float2*>(&As[(mr + 8) * AS_PAD + k0 + 2 * tig]);
                float2 f2 = *reinterpret_cast<const float2*>(&As[mr * AS_PAD + k0 + 2 * tig + 8]);
                float2 f3 = *reinterpret_cast<const float2*>(&As[(mr + 8) * AS_PAD + k0 + 2 * tig + 8]);
                bf16split2(f0, ahi[mt][0], alo[mt][0]);
                bf16split2(f1, ahi[mt][1], alo[mt][1]);
                bf16split2(f2, ahi[mt][2], alo[mt][2]);
                bf16split2(f3, ahi[mt][3], alo[mt][3]);
            }
#pragma unroll
            for (int nt = 0; nt < 8; nt++) {
                int n = n0w + nt * 8 + grp;
                unsigned int bh0 = BsHi[(k2b + tig) * BS_PAD + n];
                unsigned int bh1 = BsHi[(k2b + tig + 4) * BS_PAD + n];
                unsigned int bl0 = BsLo[(k2b + tig) * BS_PAD + n];
                unsigned int bl1 = BsLo[(k2b + tig + 4) * BS_PAD + n];
#pragma unroll
                for (int mt = 0; mt < 2; mt++) {
                    MMA_BF16(acc[mt][nt], ahi[mt][0], ahi[mt][1], ahi[mt][2], ahi[mt][3], bh0, bh1);
                    MMA_BF16(acc[mt][nt], alo[mt][0], alo[mt][1], alo[mt][2], alo[mt][3], bh0, bh1);
                    MMA_BF16(acc[mt][nt], ahi[mt][0], ahi[mt][1], ahi[mt][2], ahi[mt][3], bl0, bl1);
                }
            }
        }
        __syncthreads();
    }

    // --- epilogue: +bias, relu, float2 stores ---
#pragma unroll
    for (int mt = 0; mt < 2; mt++) {
        int gm0 = rowBase + m0w + mt * 16 + grp;
        int gm1 = gm0 + 8;
#pragma unroll
        for (int nt = 0; nt < 8; nt++) {
            int n = n0w + nt * 8 + 2 * tig;
            float2 bb = *reinterpret_cast<const float2*>(bl + n);
            if (gm0 < N_NODES) {
                float2 o;
                o.x = fmaxf(acc[mt][nt][0] + bb.x, 0.0f);
                o.y = fmaxf(acc[mt][nt][1] + bb.y, 0.0f);
                *reinterpret_cast<float2*>(hout + (size_t)gm0 * HID + n) = o;
            }
            if (gm1 < N_NODES) {
                float2 o;
                o.x = fmaxf(acc[mt][nt][2] + bb.x, 0.0f);
                o.y = fmaxf(acc[mt][nt][3] + bb.y, 0.0f);
                *reinterpret_cast<float2*>(hout + (size_t)gm1 * HID + n) = o;
            }
        }
    }
}

// ---------------- pooled = segment_sum(h, batch) (batch sorted) ----------------
__global__ __launch_bounds__(128) void pool_kernel(
    const float* __restrict__ hin, const int* __restrict__ batch)
{
    int base = blockIdx.x * 128;
    int c = threadIdx.x;
    int limit = N_NODES - base;
    if (limit > 128) limit = 128;
    if (limit <= 0) return;
    int cur = __ldg(&batch[base]);
    float acc = 0.0f;
    for (int r = 0; r < limit; r++) {
        int b = __ldg(&batch[base + r]);
        if (b != cur) {
            atomicAdd(&g_pooled[cur * HID + c], acc);
            acc = 0.0f;
            cur = b;
        }
        acc += hin[(size_t)(base + r) * HID + c];
    }
    atomicAdd(&g_pooled[cur * HID + c], acc);
}

// ---------------- batchnorm stats ----------------
__global__ __launch_bounds__(128) void bn_kernel(
    const float* __restrict__ gamma, const float* __restrict__ beta)
{
    int c = threadIdx.x;
    float s = 0.0f, s2 = 0.0f;
    for (int g = 0; g < N_GRAPHS; g++) {
        float v = g_pooled[g * HID + c];
        s += v;
        s2 += v * v;
    }
    float mu = s * (1.0f / N_GRAPHS);
    float var = s2 * (1.0f / N_GRAPHS) - mu * mu;
    float sc = gamma[c] * rsqrtf(var + BN_EPS);
    g_scale[c] = sc;
    g_shift[c] = beta[c] - mu * sc;
}

// ---------------- final FC ----------------
__global__ __launch_bounds__(64) void final_kernel(
    const float* __restrict__ fcW, const float* __restrict__ fcb,
    float* __restrict__ out)
{
    __shared__ float row[HID];
    int g = blockIdx.x;
    int l = threadIdx.x;
    for (int c = l; c < HID; c += 64)
        row[c] = g_pooled[g * HID + c] * g_scale[c] + g_shift[c];
    __syncthreads();
    float acc = fcb[l];
#pragma unroll
    for (int c = 0; c < HID; c++)
        acc += row[c] * __ldg(&fcW[c * LATENT + l]);
    out[g * LATENT + l] = acc;
}

// ---------------- launch ----------------
extern "C" void kernel_launch(void* const* d_in, const int* in_sizes, int n_in,
                              void* d_out, int out_size)
{
    const float* x     = (const float*)d_in[0];
    const int*   ei    = (const int*)d_in[1];
    const int*   batch = (const int*)d_in[2];
    const float* Wl    = (const float*)d_in[3];
    const float* bl    = (const float*)d_in[4];
    const float* Wr    = (const float*)d_in[5];
    const float* gamma = (const float*)d_in[6];
    const float* beta  = (const float*)d_in[7];
    const float* fcW   = (const float*)d_in[8];
    const float* fcb   = (const float*)d_in[9];
    float* out = (float*)d_out;

    const int E = in_sizes[1] / 2;
    const int* src = ei;
    const int* dst = ei + E;

    float *h0, *h1, *pooled;
    int *deg;
    unsigned int *bhi, *blo;
    cudaGetSymbolAddress((void**)&h0, g_h0);
    cudaGetSymbolAddress((void**)&h1, g_h1);
    cudaGetSymbolAddress((void**)&pooled, g_pooled);
    cudaGetSymbolAddress((void**)&deg, g_deg);
    cudaGetSymbolAddress((void**)&bhi, g_Bhi);
    cudaGetSymbolAddress((void**)&blo, g_Blo);

    cudaFuncSetAttribute(sage_mma_kernel,
                         cudaFuncAttributeMaxDynamicSharedMemorySize,
                         SMEM_TOTAL_BYTES);

    // ---- CSR build + weight split ----
    zero_i<<<(N_NODES + 255) / 256, 256>>>(deg, N_NODES);
    zero_f<<<(N_GRAPHS * HID + 255) / 256, 256>>>(pooled, N_GRAPHS * HID);
    count_kernel<<<(E + 255) / 256, 256>>>(dst, E);
    scan_blocksum<<<SCAN_BLOCKS, 256>>>();
    scan_top<<<1, 256>>>();
    scan_low<<<SCAN_BLOCKS, 256>>>(E);
    fill_kernel<<<(E + 255) / 256, 256>>>(src, dst, E);
    bsplit_kernel<<<(3 * 128 * 128 + 255) / 256, 256>>>(Wl, Wr);

    const float* hin = x;
    float* houts[3] = { h0, h1, h0 };
    for (int layer = 0; layer < 3; layer++) {
        gather_kernel<<<N_NODES, 128>>>(hin);
        sage_mma_kernel<<<GEMM_BLOCKS, 256, SMEM_TOTAL_BYTES>>>(
            hin, bhi + layer * 128 * 128, blo + layer * 128 * 128,
            bl + layer * HID, houts[layer]);
        hin = houts[layer];
    }

    pool_kernel<<<(N_NODES + 127) / 128, 128>>>(h0, batch);
    bn_kernel<<<1, 128>>>(gamma, beta);
    final_kernel<<<N_GRAPHS, 64>>>(fcW, fcb, out);
}

// round 7
// speedup vs baseline: 3.0047x; 1.0843x over previous
#include <cuda_runtime.h>
#include <cuda_bf16.h>
#include <cstdint>

#define N_NODES 50000
#define HID 128
#define LATENT 64
#define N_GRAPHS 256
#define BN_EPS 1e-5f
#define SCAN_BLOCKS 196          // 196*256 >= 50000
#define GEMM_BLOCKS 391          // ceil(50000/128)

#define A_PITCH 20               // uints per row in A smem (16 data + 4 pad) -> conflict-free frags
#define BS_PAD 136               // conflict-free B frag loads (8*tig+grp distinct)

// ---------------- device scratch (static, no allocation) ----------------
__device__ float g_h0[N_NODES * HID];
__device__ float g_h1[N_NODES * HID];
__device__ int   g_deg[N_NODES];
__device__ int   g_rowstart[N_NODES + 1];
__device__ int   g_cursor[N_NODES];
__device__ int   g_csr[800000 * 2];
__device__ int   g_blocksum[SCAN_BLOCKS];
__device__ int   g_blockoff[SCAN_BLOCKS];
__device__ float g_pooled[N_GRAPHS * HID];
__device__ float g_scale[HID];
__device__ float g_shift[HID];
// bf16 hi/lo images of operands, packed bf16x2 along k (64 uints per row of 128)
__device__ unsigned int g_gahi[N_NODES * 64];     // mean of neighbors (agg)
__device__ unsigned int g_galo[N_NODES * 64];
__device__ unsigned int g_Ah[2][N_NODES * 64];    // hin ping-pong (x -> buf 0)
__device__ unsigned int g_Al[2][N_NODES * 64];
__device__ unsigned int g_Bhi[3 * 128 * 128];     // per-layer fused [Wl;Wr], [k2][n]
__device__ unsigned int g_Blo[3 * 128 * 128];

// ---------------- utility ----------------
__global__ void zero_f(float* __restrict__ p, int n) {
    int i = blockIdx.x * blockDim.x + threadIdx.x;
    if (i < n) p[i] = 0.0f;
}
__global__ void zero_i(int* __restrict__ p, int n) {
    int i = blockIdx.x * blockDim.x + threadIdx.x;
    if (i < n) p[i] = 0;
}
__global__ void count_kernel(const int* __restrict__ dst, int nE) {
    int i = blockIdx.x * blockDim.x + threadIdx.x;
    if (i < nE) atomicAdd(&g_deg[dst[i]], 1);
}

// ---------------- parallel 3-phase scan over degrees ----------------
__global__ __launch_bounds__(256) void scan_blocksum() {
    __shared__ int red[256];
    int t = threadIdx.x;
    int i = blockIdx.x * 256 + t;
    int v = (i < N_NODES) ? g_deg[i] : 0;
    red[t] = v;
    __syncthreads();
    for (int off = 128; off > 0; off >>= 1) {
        if (t < off) red[t] += red[t + off];
        __syncthreads();
    }
    if (t == 0) g_blocksum[blockIdx.x] = red[0];
}
__global__ __launch_bounds__(256) void scan_top() {
    __shared__ int s[256];
    int t = threadIdx.x;
    int v = (t < SCAN_BLOCKS) ? g_blocksum[t] : 0;
    s[t] = v;
    __syncthreads();
    for (int off = 1; off < 256; off <<= 1) {
        int u = (t >= off) ? s[t - off] : 0;
        __syncthreads();
        s[t] += u;
        __syncthreads();
    }
    if (t < SCAN_BLOCKS) g_blockoff[t] = s[t] - v;   // exclusive
}
__global__ __launch_bounds__(256) void scan_low(int nE) {
    __shared__ int s[256];
    int t = threadIdx.x;
    int i = blockIdx.x * 256 + t;
    int v = (i < N_NODES) ? g_deg[i] : 0;
    s[t] = v;
    __syncthreads();
    for (int off = 1; off < 256; off <<= 1) {
        int u = (t >= off) ? s[t - off] : 0;
        __syncthreads();
        s[t] += u;
        __syncthreads();
    }
    if (i < N_NODES) {
        int excl = g_blockoff[blockIdx.x] + s[t] - v;
        g_rowstart[i] = excl;
        g_cursor[i] = excl;
        if (i == N_NODES - 1) g_rowstart[N_NODES] = nE;
    }
}

__global__ void fill_kernel(const int* __restrict__ src,
                            const int* __restrict__ dst, int nE) {
    int i = blockIdx.x * blockDim.x + threadIdx.x;
    if (i < nE) {
        int pos = atomicAdd(&g_cursor[dst[i]], 1);
        g_csr[pos] = src[i];
    }
}

// ---------------- bf16 split helpers ----------------
__device__ __forceinline__ void bf16split2(float2 f, unsigned int& hi, unsigned int& lo) {
    asm("cvt.rn.bf16x2.f32 %0, %1, %2;" : "=r"(hi) : "f"(f.y), "f"(f.x));
    float hx = __uint_as_float(hi << 16);
    float hy = __uint_as_float(hi & 0xFFFF0000u);
    asm("cvt.rn.bf16x2.f32 %0, %1, %2;" : "=r"(lo) : "f"(f.y - hy), "f"(f.x - hx));
}

// ---------------- weight split: fused B[L][k][n] -> packed bf16x2 hi/lo ----------------
// g_Bhi[L][k2][n] holds (B[2*k2][n], B[2*k2+1][n]) as bf16x2 (low = even k).
__global__ void bsplit_kernel(const float* __restrict__ Wl,
                              const float* __restrict__ Wr) {
    int i = blockIdx.x * blockDim.x + threadIdx.x;
    if (i >= 3 * 128 * 128) return;
    int L = i >> 14;
    int r = i & 16383;
    int k2 = r >> 7;
    int n = r & 127;
    int k = k2 << 1;          // even; k and k+1 in the same matrix
    const float* W = (k < 128) ? (Wl + L * 16384 + k * 128)
                               : (Wr + L * 16384 + (k - 128) * 128);
    unsigned int hi, lo;
    bf16split2(make_float2(W[n], W[128 + n]), hi, lo);
    g_Bhi[i] = hi;
    g_Blo[i] = lo;
}

// ---------------- x split: fp32 [N][128] -> bf16x2 hi/lo [N][64] ----------------
__global__ void xsplit_kernel(const float* __restrict__ x) {
    int i = blockIdx.x * blockDim.x + threadIdx.x;
    if (i >= N_NODES * 64) return;
    int row = i >> 6;
    int n2 = i & 63;
    float2 v = *reinterpret_cast<const float2*>(x + (size_t)row * HID + 2 * n2);
    unsigned int hi, lo;
    bf16split2(v, hi, lo);
    g_Ah[0][i] = hi;
    g_Al[0][i] = lo;
}

// ---------------- gather: warp per node, float4 per lane, bf16 hi/lo out ----------------
__global__ __launch_bounds__(256) void gather_kernel(const float* __restrict__ hin) {
    int node = blockIdx.x * 8 + (threadIdx.x >> 5);
    if (node >= N_NODES) return;
    int lane = threadIdx.x & 31;
    int s0 = g_rowstart[node];
    int s1 = g_rowstart[node + 1];
    float4 acc = make_float4(0.f, 0.f, 0.f, 0.f);
    int j = s0;
    for (; j + 4 <= s1; j += 4) {
        int i0 = __ldg(&g_csr[j + 0]);
        int i1 = __ldg(&g_csr[j + 1]);
        int i2 = __ldg(&g_csr[j + 2]);
        int i3 = __ldg(&g_csr[j + 3]);
        float4 a = *reinterpret_cast<const float4*>(hin + (size_t)i0 * HID + lane * 4);
        float4 b = *reinterpret_cast<const float4*>(hin + (size_t)i1 * HID + lane * 4);
        float4 d = *reinterpret_cast<const float4*>(hin + (size_t)i2 * HID + lane * 4);
        float4 e = *reinterpret_cast<const float4*>(hin + (size_t)i3 * HID + lane * 4);
        acc.x += (a.x + b.x) + (d.x + e.x);
        acc.y += (a.y + b.y) + (d.y + e.y);
        acc.z += (a.z + b.z) + (d.z + e.z);
        acc.w += (a.w + b.w) + (d.w + e.w);
    }
    for (; j < s1; j++) {
        float4 a = *reinterpret_cast<const float4*>(
            hin + (size_t)__ldg(&g_csr[j]) * HID + lane * 4);
        acc.x += a.x; acc.y += a.y; acc.z += a.z; acc.w += a.w;
    }
    int deg = s1 - s0;
    float inv = 1.0f / (float)(deg > 0 ? deg : 1);
    acc.x *= inv; acc.y *= inv; acc.z *= inv; acc.w *= inv;
    unsigned int h0, l0, h1, l1;
    bf16split2(make_float2(acc.x, acc.y), h0, l0);
    bf16split2(make_float2(acc.z, acc.w), h1, l1);
    uint2 vh = make_uint2(h0, h1);
    uint2 vl = make_uint2(l0, l1);
    *reinterpret_cast<uint2*>(g_gahi + (size_t)node * 64 + lane * 2) = vh;
    *reinterpret_cast<uint2*>(g_galo + (size_t)node * 64 + lane * 2) = vl;
}

// ---------------- bf16 3-pass MMA GEMM (pre-split A, no inner-loop cvt) ----------------
// hout[m,n] = relu( [agg|hin][m,:] @ (Bhi+Blo) + bl[n] ),  K=256
// block 128x128, 8 warps (4m x 2n), warp tile 32x64, mma m16n8k16 bf16.
#define MMA_BF16(d, a0, a1, a2, a3, b0, b1)                                 \
    asm volatile("mma.sync.aligned.m16n8k16.row.col.f32.bf16.bf16.f32 "     \
                 "{%0,%1,%2,%3}, {%4,%5,%6,%7}, {%8,%9}, {%0,%1,%2,%3};"    \
                 : "+f"(d[0]), "+f"(d[1]), "+f"(d[2]), "+f"(d[3])           \
                 : "r"(a0), "r"(a1), "r"(a2), "r"(a3), "r"(b0), "r"(b1))

__global__ __launch_bounds__(256) void sage_mma_kernel(
    const unsigned int* __restrict__ Ah,     // hin hi [N][64]
    const unsigned int* __restrict__ Al,     // hin lo
    const unsigned int* __restrict__ Bhi,    // [128 k2][128 n] this layer
    const unsigned int* __restrict__ Blo,
    const float* __restrict__ bl,
    float* __restrict__ hout,
    unsigned int* __restrict__ Ohi,          // next-layer hin hi [N][64]
    unsigned int* __restrict__ Olo,
    int writeBf)
{
    __shared__ unsigned int AsHi[128 * A_PITCH];
    __shared__ unsigned int AsLo[128 * A_PITCH];
    __shared__ unsigned int BsHi[16 * BS_PAD];
    __shared__ unsigned int BsLo[16 * BS_PAD];

    const int tid = threadIdx.x;
    const int lane = tid & 31;
    const int wid = tid >> 5;
    const int m0w = (wid >> 1) * 32;
    const int n0w = (wid & 1) * 64;
    const int rowBase = blockIdx.x * 128;
    const int grp = lane >> 2;   // 0..7
    const int tig = lane & 3;    // 0..3

    float acc[2][8][4];
#pragma unroll
    for (int mt = 0; mt < 2; mt++)
#pragma unroll
        for (int nt = 0; nt < 8; nt++)
#pragma unroll
            for (int q = 0; q < 4; q++) acc[mt][nt][q] = 0.0f;

    for (int kb = 0; kb < 256; kb += 32) {
        const int c = kb >> 5;              // chunk 0..7 (0-3: agg, 4-7: hin)
        // --- B chunk: 16 k2-rows x 128 n, hi+lo, uint4 coalesced ---
#pragma unroll
        for (int i = 0; i < 2; i++) {
            int idx = tid + i * 256;            // 0..511 uint4 units
            int kk2 = idx >> 5;                 // 0..15
            int nn = (idx & 31) << 2;           // 0..124
            uint4 vh = *reinterpret_cast<const uint4*>(Bhi + (c * 16 + kk2) * 128 + nn);
            *reinterpret_cast<uint4*>(&BsHi[kk2 * BS_PAD + nn]) = vh;
            uint4 vl = *reinterpret_cast<const uint4*>(Blo + (c * 16 + kk2) * 128 + nn);
            *reinterpret_cast<uint4*>(&BsLo[kk2 * BS_PAD + nn]) = vl;
        }
        // --- A chunk: pre-split bf16x2, 128 rows x 16 uints, uint4 coalesced ---
        const unsigned int* srcHi = (c < 4) ? g_gahi : Ah;
        const unsigned int* srcLo = (c < 4) ? g_galo : Al;
        const int colBase = (c & 3) * 16;
#pragma unroll
        for (int i = 0; i < 2; i++) {
            int idx = tid + i * 256;            // 0..511 uint4 units
            int row = idx >> 2;                 // 0..127
            int c4 = (idx & 3) << 2;            // 0,4,8,12
            int gm = rowBase + row;
            uint4 vh = make_uint4(0u, 0u, 0u, 0u);
            uint4 vl = make_uint4(0u, 0u, 0u, 0u);
            if (gm < N_NODES) {
                vh = *reinterpret_cast<const uint4*>(srcHi + (size_t)gm * 64 + colBase + c4);
                vl = *reinterpret_cast<const uint4*>(srcLo + (size_t)gm * 64 + colBase + c4);
            }
            *reinterpret_cast<uint4*>(&AsHi[row * A_PITCH + c4]) = vh;
            *reinterpret_cast<uint4*>(&AsLo[row * A_PITCH + c4]) = vl;
        }
        __syncthreads();

#pragma unroll
        for (int ks = 0; ks < 2; ks++) {
            const int k2b = ks * 8;
            unsigned int ahi[2][4], alo[2][4];
#pragma unroll
            for (int mt = 0; mt < 2; mt++) {
                int mr = m0w + mt * 16 + grp;
                ahi[mt][0] = AsHi[mr * A_PITCH + k2b + tig];
                ahi[mt][1] = AsHi[(mr + 8) * A_PITCH + k2b + tig];
                ahi[mt][2] = AsHi[mr * A_PITCH + k2b + tig + 4];
                ahi[mt][3] = AsHi[(mr + 8) * A_PITCH + k2b + tig + 4];
                alo[mt][0] = AsLo[mr * A_PITCH + k2b + tig];
                alo[mt][1] = AsLo[(mr + 8) * A_PITCH + k2b + tig];
                alo[mt][2] = AsLo[mr * A_PITCH + k2b + tig + 4];
                alo[mt][3] = AsLo[(mr + 8) * A_PITCH + k2b + tig + 4];
            }
#pragma unroll
            for (int nt = 0; nt < 8; nt++) {
                int n = n0w + nt * 8 + grp;
                unsigned int bh0 = BsHi[(k2b + tig) * BS_PAD + n];
                unsigned int bh1 = BsHi[(k2b + tig + 4) * BS_PAD + n];
                unsigned int bl0 = BsLo[(k2b + tig) * BS_PAD + n];
                unsigned int bl1 = BsLo[(k2b + tig + 4) * BS_PAD + n];
#pragma unroll
                for (int mt = 0; mt < 2; mt++) {
                    MMA_BF16(acc[mt][nt], ahi[mt][0], ahi[mt][1], ahi[mt][2], ahi[mt][3], bh0, bh1);
                    MMA_BF16(acc[mt][nt], alo[mt][0], alo[mt][1], alo[mt][2], alo[mt][3], bh0, bh1);
                    MMA_BF16(acc[mt][nt], ahi[mt][0], ahi[mt][1], ahi[mt][2], ahi[mt][3], bl0, bl1);
                }
            }
        }
        __syncthreads();
    }

    // --- epilogue: +bias, relu, fp32 store + bf16 hi/lo store for next layer ---
#pragma unroll
    for (int mt = 0; mt < 2; mt++) {
        int gm0 = rowBase + m0w + mt * 16 + grp;
        int gm1 = gm0 + 8;
#pragma unroll
        for (int nt = 0; nt < 8; nt++) {
            int n = n0w + nt * 8 + 2 * tig;
            float2 bb = *reinterpret_cast<const float2*>(bl + n);
            if (gm0 < N_NODES) {
                float2 o;
                o.x = fmaxf(acc[mt][nt][0] + bb.x, 0.0f);
                o.y = fmaxf(acc[mt][nt][1] + bb.y, 0.0f);
                *reinterpret_cast<float2*>(hout + (size_t)gm0 * HID + n) = o;
                if (writeBf) {
                    unsigned int hi, lo;
                    bf16split2(o, hi, lo);
                    Ohi[(size_t)gm0 * 64 + (n >> 1)] = hi;
                    Olo[(size_t)gm0 * 64 + (n >> 1)] = lo;
                }
            }
            if (gm1 < N_NODES) {
                float2 o;
                o.x = fmaxf(acc[mt][nt][2] + bb.x, 0.0f);
                o.y = fmaxf(acc[mt][nt][3] + bb.y, 0.0f);
                *reinterpret_cast<float2*>(hout + (size_t)gm1 * HID + n) = o;
                if (writeBf) {
                    unsigned int hi, lo;
                    bf16split2(o, hi, lo);
                    Ohi[(size_t)gm1 * 64 + (n >> 1)] = hi;
                    Olo[(size_t)gm1 * 64 + (n >> 1)] = lo;
                }
            }
        }
    }
}

// ---------------- pooled = segment_sum(h, batch) (batch sorted) ----------------
__global__ __launch_bounds__(128) void pool_kernel(
    const float* __restrict__ hin, const int* __restrict__ batch)
{
    int base = blockIdx.x * 128;
    int c = threadIdx.x;
    int limit = N_NODES - base;
    if (limit > 128) limit = 128;
    if (limit <= 0) return;
    int cur = __ldg(&batch[base]);
    float acc = 0.0f;
    for (int r = 0; r < limit; r++) {
        int b = __ldg(&batch[base + r]);
        if (b != cur) {
            atomicAdd(&g_pooled[cur * HID + c], acc);
            acc = 0.0f;
            cur = b;
        }
        acc += hin[(size_t)(base + r) * HID + c];
    }
    atomicAdd(&g_pooled[cur * HID + c], acc);
}

// ---------------- batchnorm stats ----------------
__global__ __launch_bounds__(128) void bn_kernel(
    const float* __restrict__ gamma, const float* __restrict__ beta)
{
    int c = threadIdx.x;
    float s = 0.0f, s2 = 0.0f;
    for (int g = 0; g < N_GRAPHS; g++) {
        float v = g_pooled[g * HID + c];
        s += v;
        s2 += v * v;
    }
    float mu = s * (1.0f / N_GRAPHS);
    float var = s2 * (1.0f / N_GRAPHS) - mu * mu;
    float sc = gamma[c] * rsqrtf(var + BN_EPS);
    g_scale[c] = sc;
    g_shift[c] = beta[c] - mu * sc;
}

// ---------------- final FC ----------------
__global__ __launch_bounds__(64) void final_kernel(
    const float* __restrict__ fcW, const float* __restrict__ fcb,
    float* __restrict__ out)
{
    __shared__ float row[HID];
    int g = blockIdx.x;
    int l = threadIdx.x;
    for (int c = l; c < HID; c += 64)
        row[c] = g_pooled[g * HID + c] * g_scale[c] + g_shift[c];
    __syncthreads();
    float acc = fcb[l];
#pragma unroll
    for (int c = 0; c < HID; c++)
        acc += row[c] * __ldg(&fcW[c * LATENT + l]);
    out[g * LATENT + l] = acc;
}

// ---------------- launch ----------------
extern "C" void kernel_launch(void* const* d_in, const int* in_sizes, int n_in,
                              void* d_out, int out_size)
{
    const float* x     = (const float*)d_in[0];
    const int*   ei    = (const int*)d_in[1];
    const int*   batch = (const int*)d_in[2];
    const float* Wl    = (const float*)d_in[3];
    const float* bl    = (const float*)d_in[4];
    const float* Wr    = (const float*)d_in[5];
    const float* gamma = (const float*)d_in[6];
    const float* beta  = (const float*)d_in[7];
    const float* fcW   = (const float*)d_in[8];
    const float* fcb   = (const float*)d_in[9];
    float* out = (float*)d_out;

    const int E = in_sizes[1] / 2;
    const int* src = ei;
    const int* dst = ei + E;

    float *h0, *h1, *pooled;
    int *deg;
    unsigned int *bhi, *blo, *ah, *al;
    cudaGetSymbolAddress((void**)&h0, g_h0);
    cudaGetSymbolAddress((void**)&h1, g_h1);
    cudaGetSymbolAddress((void**)&pooled, g_pooled);
    cudaGetSymbolAddress((void**)&deg, g_deg);
    cudaGetSymbolAddress((void**)&bhi, g_Bhi);
    cudaGetSymbolAddress((void**)&blo, g_Blo);
    cudaGetSymbolAddress((void**)&ah, g_Ah);
    cudaGetSymbolAddress((void**)&al, g_Al);

    // ---- CSR build + weight/x split ----
    zero_i<<<(N_NODES + 255) / 256, 256>>>(deg, N_NODES);
    zero_f<<<(N_GRAPHS * HID + 255) / 256, 256>>>(pooled, N_GRAPHS * HID);
    count_kernel<<<(E + 255) / 256, 256>>>(dst, E);
    scan_blocksum<<<SCAN_BLOCKS, 256>>>();
    scan_top<<<1, 256>>>();
    scan_low<<<SCAN_BLOCKS, 256>>>(E);
    fill_kernel<<<(E + 255) / 256, 256>>>(src, dst, E);
    bsplit_kernel<<<(3 * 128 * 128 + 255) / 256, 256>>>(Wl, Wr);
    xsplit_kernel<<<(N_NODES * 64 + 255) / 256, 256>>>(x);

    const float* hin_f32 = x;
    float* houts[3] = { h0, h1, h0 };
    for (int layer = 0; layer < 3; layer++) {
        int cur = layer & 1;          // hin bf16 buffer
        int nxt = cur ^ 1;
        gather_kernel<<<(N_NODES + 7) / 8, 256>>>(hin_f32);
        sage_mma_kernel<<<GEMM_BLOCKS, 256>>>(
            ah + cur * (N_NODES * 64), al + cur * (N_NODES * 64),
            bhi + layer * 128 * 128, blo + layer * 128 * 128,
            bl + layer * HID, houts[layer],
            ah + nxt * (N_NODES * 64), al + nxt * (N_NODES * 64),
            (layer < 2) ? 1 : 0);
        hin_f32 = houts[layer];
    }

    pool_kernel<<<(N_NODES + 127) / 128, 128>>>(h0, batch);
    bn_kernel<<<1, 128>>>(gamma, beta);
    final_kernel<<<N_GRAPHS, 64>>>(fcW, fcb, out);
}

// round 8
// speedup vs baseline: 3.9912x; 1.3283x over previous
#include <cuda_runtime.h>
#include <cuda_fp16.h>
#include <cstdint>

#define N_NODES 50000
#define HID 128
#define LATENT 64
#define N_GRAPHS 256
#define BN_EPS 1e-5f
#define SCAN_BLOCKS 196          // 196*256 >= 50000
#define GEMM_BLOCKS 391          // ceil(50000/128)

#define A_PITCH 20               // uints per A smem row (16 data + 4 pad) -> conflict-free
#define BS_PAD 136               // conflict-free B frag loads (8*tig+grp distinct)

// dynamic smem layout per buffer (bytes)
#define SM_AHI 0
#define SM_ALO 10240             // 128*20*4
#define SM_BHI 20480
#define SM_BLO 29184             // +16*136*4
#define SM_BUF 37888
#define SM_TOTAL (2 * SM_BUF)

// ---------------- device scratch (static, no allocation) ----------------
__device__ float g_hf32[N_NODES * HID];           // fp32 h (layer 2 only, for pool)
__device__ int   g_deg[N_NODES];
__device__ int   g_rowstart[N_NODES + 1];
__device__ int   g_cursor[N_NODES];
__device__ int   g_csr[800000 * 2];
__device__ int   g_blocksum[SCAN_BLOCKS];
__device__ int   g_blockoff[SCAN_BLOCKS];
__device__ float g_pooled[N_GRAPHS * HID];
__device__ float g_scale[HID];
__device__ float g_shift[HID];
// fp16x2-packed hi/lo images (64 uints per 128-ch row)
__device__ unsigned int g_gahi[N_NODES * 64];     // mean of neighbors
__device__ unsigned int g_galo[N_NODES * 64];
__device__ unsigned int g_Ah[2][N_NODES * 64];    // hin ping-pong (x -> buf 0)
__device__ unsigned int g_Al[2][N_NODES * 64];
__device__ unsigned int g_Bhi[3 * 128 * 128];     // per-layer fused [Wl;Wr], [k2][n]
__device__ unsigned int g_Blo[3 * 128 * 128];

// ---------------- helpers ----------------
__device__ __forceinline__ uint32_t smem_u32(const void* p) {
    uint32_t a;
    asm("{ .reg .u64 t; cvta.to.shared.u64 t, %1; cvt.u32.u64 %0, t; }"
        : "=r"(a) : "l"(p));
    return a;
}
__device__ __forceinline__ void f16split2(float2 f, unsigned int& hi, unsigned int& lo) {
    __half2 h = __float22half2_rn(f);
    hi = *reinterpret_cast<unsigned int*>(&h);
    float2 hf = __half22float2(h);
    __half2 l = __float22half2_rn(make_float2(f.x - hf.x, f.y - hf.y));
    lo = *reinterpret_cast<unsigned int*>(&l);
}
__device__ __forceinline__ void acc_u2(float4& acc, uint2 u) {
    float2 f0 = __half22float2(*reinterpret_cast<__half2*>(&u.x));
    float2 f1 = __half22float2(*reinterpret_cast<__half2*>(&u.y));
    acc.x += f0.x; acc.y += f0.y; acc.z += f1.x; acc.w += f1.y;
}

#define CP_ASYNC16(dst, src, bytes) \
    asm volatile("cp.async.cg.shared.global [%0], [%1], 16, %2;" \
                 :: "r"(dst), "l"(src), "r"(bytes))
#define CP_COMMIT() asm volatile("cp.async.commit_group;" ::: "memory")
#define CP_WAIT1()  asm volatile("cp.async.wait_group 1;" ::: "memory")
#define CP_WAIT0()  asm volatile("cp.async.wait_group 0;" ::: "memory")

// ---------------- utility ----------------
__global__ void zero_f(float* __restrict__ p, int n) {
    int i = blockIdx.x * blockDim.x + threadIdx.x;
    if (i < n) p[i] = 0.0f;
}
__global__ void zero_i(int* __restrict__ p, int n) {
    int i = blockIdx.x * blockDim.x + threadIdx.x;
    if (i < n) p[i] = 0;
}
__global__ void count_kernel(const int* __restrict__ dst, int nE) {
    int i = blockIdx.x * blockDim.x + threadIdx.x;
    if (i < nE) atomicAdd(&g_deg[dst[i]], 1);
}

// ---------------- parallel 3-phase scan over degrees ----------------
__global__ __launch_bounds__(256) void scan_blocksum() {
    __shared__ int red[256];
    int t = threadIdx.x;
    int i = blockIdx.x * 256 + t;
    int v = (i < N_NODES) ? g_deg[i] : 0;
    red[t] = v;
    __syncthreads();
    for (int off = 128; off > 0; off >>= 1) {
        if (t < off) red[t] += red[t + off];
        __syncthreads();
    }
    if (t == 0) g_blocksum[blockIdx.x] = red[0];
}
__global__ __launch_bounds__(256) void scan_top() {
    __shared__ int s[256];
    int t = threadIdx.x;
    int v = (t < SCAN_BLOCKS) ? g_blocksum[t] : 0;
    s[t] = v;
    __syncthreads();
    for (int off = 1; off < 256; off <<= 1) {
        int u = (t >= off) ? s[t - off] : 0;
        __syncthreads();
        s[t] += u;
        __syncthreads();
    }
    if (t < SCAN_BLOCKS) g_blockoff[t] = s[t] - v;   // exclusive
}
__global__ __launch_bounds__(256) void scan_low(int nE) {
    __shared__ int s[256];
    int t = threadIdx.x;
    int i = blockIdx.x * 256 + t;
    int v = (i < N_NODES) ? g_deg[i] : 0;
    s[t] = v;
    __syncthreads();
    for (int off = 1; off < 256; off <<= 1) {
        int u = (t >= off) ? s[t - off] : 0;
        __syncthreads();
        s[t] += u;
        __syncthreads();
    }
    if (i < N_NODES) {
        int excl = g_blockoff[blockIdx.x] + s[t] - v;
        g_rowstart[i] = excl;
        g_cursor[i] = excl;
        if (i == N_NODES - 1) g_rowstart[N_NODES] = nE;
    }
}

__global__ void fill_kernel(const int* __restrict__ src,
                            const int* __restrict__ dst, int nE) {
    int i = blockIdx.x * blockDim.x + threadIdx.x;
    if (i < nE) {
        int pos = atomicAdd(&g_cursor[dst[i]], 1);
        g_csr[pos] = src[i];
    }
}

// ---------------- weight split: fused B[L][k][n] -> packed fp16x2 hi/lo ----------------
__global__ void bsplit_kernel(const float* __restrict__ Wl,
                              const float* __restrict__ Wr) {
    int i = blockIdx.x * blockDim.x + threadIdx.x;
    if (i >= 3 * 128 * 128) return;
    int L = i >> 14;
    int r = i & 16383;
    int k2 = r >> 7;
    int n = r & 127;
    int k = k2 << 1;          // even; k and k+1 in the same matrix
    const float* W = (k < 128) ? (Wl + L * 16384 + k * 128)
                               : (Wr + L * 16384 + (k - 128) * 128);
    unsigned int hi, lo;
    f16split2(make_float2(W[n], W[128 + n]), hi, lo);
    g_Bhi[i] = hi;
    g_Blo[i] = lo;
}

// ---------------- x split: fp32 [N][128] -> fp16x2 hi/lo [N][64] ----------------
__global__ void xsplit_kernel(const float* __restrict__ x) {
    int i = blockIdx.x * blockDim.x + threadIdx.x;
    if (i >= N_NODES * 64) return;
    int row = i >> 6;
    int n2 = i & 63;
    float2 v = *reinterpret_cast<const float2*>(x + (size_t)row * HID + 2 * n2);
    unsigned int hi, lo;
    f16split2(v, hi, lo);
    g_Ah[0][i] = hi;
    g_Al[0][i] = lo;
}

// ---------------- gather: warp per node, fp16-hi input, fp16 hi/lo output ----------------
__global__ __launch_bounds__(256) void gather_kernel(const unsigned int* __restrict__ h16) {
    int node = blockIdx.x * 8 + (threadIdx.x >> 5);
    if (node >= N_NODES) return;
    int lane = threadIdx.x & 31;
    int s0 = g_rowstart[node];
    int s1 = g_rowstart[node + 1];
    float4 acc = make_float4(0.f, 0.f, 0.f, 0.f);
    int j = s0;
    for (; j + 4 <= s1; j += 4) {
        int i0 = __ldg(&g_csr[j + 0]);
        int i1 = __ldg(&g_csr[j + 1]);
        int i2 = __ldg(&g_csr[j + 2]);
        int i3 = __ldg(&g_csr[j + 3]);
        uint2 a = *reinterpret_cast<const uint2*>(h16 + (size_t)i0 * 64 + lane * 2);
        uint2 b = *reinterpret_cast<const uint2*>(h16 + (size_t)i1 * 64 + lane * 2);
        uint2 d = *reinterpret_cast<const uint2*>(h16 + (size_t)i2 * 64 + lane * 2);
        uint2 e = *reinterpret_cast<const uint2*>(h16 + (size_t)i3 * 64 + lane * 2);
        acc_u2(acc, a); acc_u2(acc, b); acc_u2(acc, d); acc_u2(acc, e);
    }
    for (; j < s1; j++) {
        uint2 a = *reinterpret_cast<const uint2*>(
            h16 + (size_t)__ldg(&g_csr[j]) * 64 + lane * 2);
        acc_u2(acc, a);
    }
    int deg = s1 - s0;
    float inv = 1.0f / (float)(deg > 0 ? deg : 1);
    acc.x *= inv; acc.y *= inv; acc.z *= inv; acc.w *= inv;
    unsigned int h0, l0, h1, l1;
    f16split2(make_float2(acc.x, acc.y), h0, l0);
    f16split2(make_float2(acc.z, acc.w), h1, l1);
    *reinterpret_cast<uint2*>(g_gahi + (size_t)node * 64 + lane * 2) = make_uint2(h0, h1);
    *reinterpret_cast<uint2*>(g_galo + (size_t)node * 64 + lane * 2) = make_uint2(l0, l1);
}

// ---------------- fp16 3-pass MMA GEMM, cp.async double-buffered ----------------
// hout[m,n] = relu( [agg|hin][m,:] @ (Bhi+Blo) + bl[n] ),  K=256
// block 128x128, 8 warps (4m x 2n), warp tile 32x64, mma m16n8k16 f16.
#define MMA_F16(d, a0, a1, a2, a3, b0, b1)                                  \
    asm volatile("mma.sync.aligned.m16n8k16.row.col.f32.f16.f16.f32 "       \
                 "{%0,%1,%2,%3}, {%4,%5,%6,%7}, {%8,%9}, {%0,%1,%2,%3};"    \
                 : "+f"(d[0]), "+f"(d[1]), "+f"(d[2]), "+f"(d[3])           \
                 : "r"(a0), "r"(a1), "r"(a2), "r"(a3), "r"(b0), "r"(b1))

__global__ __launch_bounds__(256) void sage_mma_kernel(
    const unsigned int* __restrict__ Ah,     // hin hi [N][64]
    const unsigned int* __restrict__ Al,     // hin lo
    const unsigned int* __restrict__ Bhi,    // [128 k2][128 n] this layer
    const unsigned int* __restrict__ Blo,
    const float* __restrict__ bl,
    float* __restrict__ hout,                // fp32 out (if writeF32)
    unsigned int* __restrict__ Ohi,          // next-layer hin hi (if writeBf)
    unsigned int* __restrict__ Olo,
    int writeBf, int writeF32)
{
    extern __shared__ unsigned char dynsmem[];
    const uint32_t sbase = smem_u32(dynsmem);

    const int tid = threadIdx.x;
    const int lane = tid & 31;
    const int wid = tid >> 5;
    const int m0w = (wid >> 1) * 32;
    const int n0w = (wid & 1) * 64;
    const int rowBase = blockIdx.x * 128;
    const int grp = lane >> 2;   // 0..7
    const int tig = lane & 3;    // 0..3

    // per-thread copy slots (2 x uint4 each for A and B)
    int bk[2], bn[2], arow[2], ac4[2];
#pragma unroll
    for (int i = 0; i < 2; i++) {
        int idx = tid + i * 256;
        bk[i] = idx >> 5;             // 0..15
        bn[i] = (idx & 31) << 2;      // 0..124
        arow[i] = idx >> 2;           // 0..127
        ac4[i] = (idx & 3) << 2;      // 0,4,8,12
    }

    float acc[2][8][4];
#pragma unroll
    for (int mt = 0; mt < 2; mt++)
#pragma unroll
        for (int nt = 0; nt < 8; nt++)
#pragma unroll
            for (int q = 0; q < 4; q++) acc[mt][nt][q] = 0.0f;

    // chunk issue: c = 0..7 (0-3 agg, 4-7 hin), buf = target buffer
    auto issue = [&](int c, int buf) {
        const uint32_t sb = sbase + buf * SM_BUF;
        const unsigned int* srcHi = (c < 4) ? g_gahi : Ah;
        const unsigned int* srcLo = (c < 4) ? g_galo : Al;
        const int colBase = (c & 3) * 16;
#pragma unroll
        for (int i = 0; i < 2; i++) {
            const unsigned int* bgh = Bhi + (c * 16 + bk[i]) * 128 + bn[i];
            const unsigned int* bgl = Blo + (c * 16 + bk[i]) * 128 + bn[i];
            CP_ASYNC16(sb + SM_BHI + (bk[i] * BS_PAD + bn[i]) * 4, bgh, 16);
            CP_ASYNC16(sb + SM_BLO + (bk[i] * BS_PAD + bn[i]) * 4, bgl, 16);
            int gm = rowBase + arow[i];
            int valid = (gm < N_NODES) ? 16 : 0;
            const unsigned int* agh = srcHi + (size_t)gm * 64 + colBase + ac4[i];
            const unsigned int* agl = srcLo + (size_t)gm * 64 + colBase + ac4[i];
            CP_ASYNC16(sb + SM_AHI + (arow[i] * A_PITCH + ac4[i]) * 4, agh, valid);
            CP_ASYNC16(sb + SM_ALO + (arow[i] * A_PITCH + ac4[i]) * 4, agl, valid);
        }
        CP_COMMIT();
    };

    issue(0, 0);

    for (int c = 0; c < 8; c++) {
        const int buf = c & 1;
        if (c < 7) { issue(c + 1, buf ^ 1); CP_WAIT1(); }
        else CP_WAIT0();
        __syncthreads();

        const unsigned int* AsHi = reinterpret_cast<const unsigned int*>(dynsmem + buf * SM_BUF + SM_AHI);
        const unsigned int* AsLo = reinterpret_cast<const unsigned int*>(dynsmem + buf * SM_BUF + SM_ALO);
        const unsigned int* BsHi = reinterpret_cast<const unsigned int*>(dynsmem + buf * SM_BUF + SM_BHI);
        const unsigned int* BsLo = reinterpret_cast<const unsigned int*>(dynsmem + buf * SM_BUF + SM_BLO);

#pragma unroll
        for (int ks = 0; ks < 2; ks++) {
            const int k2b = ks * 8;
            unsigned int ahi[2][4], alo[2][4];
#pragma unroll
            for (int mt = 0; mt < 2; mt++) {
                int mr = m0w + mt * 16 + grp;
                ahi[mt][0] = AsHi[mr * A_PITCH + k2b + tig];
                ahi[mt][1] = AsHi[(mr + 8) * A_PITCH + k2b + tig];
                ahi[mt][2] = AsHi[mr * A_PITCH + k2b + tig + 4];
                ahi[mt][3] = AsHi[(mr + 8) * A_PITCH + k2b + tig + 4];
                alo[mt][0] = AsLo[mr * A_PITCH + k2b + tig];
                alo[mt][1] = AsLo[(mr + 8) * A_PITCH + k2b + tig];
                alo[mt][2] = AsLo[mr * A_PITCH + k2b + tig + 4];
                alo[mt][3] = AsLo[(mr + 8) * A_PITCH + k2b + tig + 4];
            }
#pragma unroll
            for (int nt = 0; nt < 8; nt++) {
                int n = n0w + nt * 8 + grp;
                unsigned int bh0 = BsHi[(k2b + tig) * BS_PAD + n];
                unsigned int bh1 = BsHi[(k2b + tig + 4) * BS_PAD + n];
                unsigned int bl0 = BsLo[(k2b + tig) * BS_PAD + n];
                unsigned int bl1 = BsLo[(k2b + tig + 4) * BS_PAD + n];
#pragma unroll
                for (int mt = 0; mt < 2; mt++) {
                    MMA_F16(acc[mt][nt], ahi[mt][0], ahi[mt][1], ahi[mt][2], ahi[mt][3], bh0, bh1);
                    MMA_F16(acc[mt][nt], alo[mt][0], alo[mt][1], alo[mt][2], alo[mt][3], bh0, bh1);
                    MMA_F16(acc[mt][nt], ahi[mt][0], ahi[mt][1], ahi[mt][2], ahi[mt][3], bl0, bl1);
                }
            }
        }
        __syncthreads();
    }

    // --- epilogue: +bias, relu; fp16 hi/lo store (layers 0,1) or fp32 (layer 2) ---
#pragma unroll
    for (int mt = 0; mt < 2; mt++) {
        int gm0 = rowBase + m0w + mt * 16 + grp;
        int gm1 = gm0 + 8;
#pragma unroll
        for (int nt = 0; nt < 8; nt++) {
            int n = n0w + nt * 8 + 2 * tig;
            float2 bb = *reinterpret_cast<const float2*>(bl + n);
            if (gm0 < N_NODES) {
                float2 o;
                o.x = fmaxf(acc[mt][nt][0] + bb.x, 0.0f);
                o.y = fmaxf(acc[mt][nt][1] + bb.y, 0.0f);
                if (writeF32)
                    *reinterpret_cast<float2*>(hout + (size_t)gm0 * HID + n) = o;
                if (writeBf) {
                    unsigned int hi, lo;
                    f16split2(o, hi, lo);
                    Ohi[(size_t)gm0 * 64 + (n >> 1)] = hi;
                    Olo[(size_t)gm0 * 64 + (n >> 1)] = lo;
                }
            }
            if (gm1 < N_NODES) {
                float2 o;
                o.x = fmaxf(acc[mt][nt][2] + bb.x, 0.0f);
                o.y = fmaxf(acc[mt][nt][3] + bb.y, 0.0f);
                if (writeF32)
                    *reinterpret_cast<float2*>(hout + (size_t)gm1 * HID + n) = o;
                if (writeBf) {
                    unsigned int hi, lo;
                    f16split2(o, hi, lo);
                    Ohi[(size_t)gm1 * 64 + (n >> 1)] = hi;
                    Olo[(size_t)gm1 * 64 + (n >> 1)] = lo;
                }
            }
        }
    }
}

// ---------------- pooled = segment_sum(h, batch) (batch sorted) ----------------
__global__ __launch_bounds__(128) void pool_kernel(
    const float* __restrict__ hin, const int* __restrict__ batch)
{
    int base = blockIdx.x * 128;
    int c = threadIdx.x;
    int limit = N_NODES - base;
    if (limit > 128) limit = 128;
    if (limit <= 0) return;
    int cur = __ldg(&batch[base]);
    float acc = 0.0f;
    for (int r = 0; r < limit; r++) {
        int b = __ldg(&batch[base + r]);
        if (b != cur) {
            atomicAdd(&g_pooled[cur * HID + c], acc);
            acc = 0.0f;
            cur = b;
        }
        acc += hin[(size_t)(base + r) * HID + c];
    }
    atomicAdd(&g_pooled[cur * HID + c], acc);
}

// ---------------- batchnorm stats ----------------
__global__ __launch_bounds__(128) void bn_kernel(
    const float* __restrict__ gamma, const float* __restrict__ beta)
{
    int c = threadIdx.x;
    float s = 0.0f, s2 = 0.0f;
    for (int g = 0; g < N_GRAPHS; g++) {
        float v = g_pooled[g * HID + c];
        s += v;
        s2 += v * v;
    }
    float mu = s * (1.0f / N_GRAPHS);
    float var = s2 * (1.0f / N_GRAPHS) - mu * mu;
    float sc = gamma[c] * rsqrtf(var + BN_EPS);
    g_scale[c] = sc;
    g_shift[c] = beta[c] - mu * sc;
}

// ---------------- final FC ----------------
__global__ __launch_bounds__(64) void final_kernel(
    const float* __restrict__ fcW, const float* __restrict__ fcb,
    float* __restrict__ out)
{
    __shared__ float row[HID];
    int g = blockIdx.x;
    int l = threadIdx.x;
    for (int c = l; c < HID; c += 64)
        row[c] = g_pooled[g * HID + c] * g_scale[c] + g_shift[c];
    __syncthreads();
    float acc = fcb[l];
#pragma unroll
    for (int c = 0; c < HID; c++)
        acc += row[c] * __ldg(&fcW[c * LATENT + l]);
    out[g * LATENT + l] = acc;
}

// ---------------- launch ----------------
extern "C" void kernel_launch(void* const* d_in, const int* in_sizes, int n_in,
                              void* d_out, int out_size)
{
    const float* x     = (const float*)d_in[0];
    const int*   ei    = (const int*)d_in[1];
    const int*   batch = (const int*)d_in[2];
    const float* Wl    = (const float*)d_in[3];
    const float* bl    = (const float*)d_in[4];
    const float* Wr    = (const float*)d_in[5];
    const float* gamma = (const float*)d_in[6];
    const float* beta  = (const float*)d_in[7];
    const float* fcW   = (const float*)d_in[8];
    const float* fcb   = (const float*)d_in[9];
    float* out = (float*)d_out;

    const int E = in_sizes[1] / 2;
    const int* src = ei;
    const int* dst = ei + E;

    float *hf32, *pooled;
    int *deg;
    unsigned int *bhi, *blo, *ah, *al;
    cudaGetSymbolAddress((void**)&hf32, g_hf32);
    cudaGetSymbolAddress((void**)&pooled, g_pooled);
    cudaGetSymbolAddress((void**)&deg, g_deg);
    cudaGetSymbolAddress((void**)&bhi, g_Bhi);
    cudaGetSymbolAddress((void**)&blo, g_Blo);
    cudaGetSymbolAddress((void**)&ah, g_Ah);
    cudaGetSymbolAddress((void**)&al, g_Al);

    cudaFuncSetAttribute(sage_mma_kernel,
                         cudaFuncAttributeMaxDynamicSharedMemorySize, SM_TOTAL);

    // ---- CSR build + weight/x split ----
    zero_i<<<(N_NODES + 255) / 256, 256>>>(deg, N_NODES);
    zero_f<<<(N_GRAPHS * HID + 255) / 256, 256>>>(pooled, N_GRAPHS * HID);
    count_kernel<<<(E + 255) / 256, 256>>>(dst, E);
    scan_blocksum<<<SCAN_BLOCKS, 256>>>();
    scan_top<<<1, 256>>>();
    scan_low<<<SCAN_BLOCKS, 256>>>(E);
    fill_kernel<<<(E + 255) / 256, 256>>>(src, dst, E);
    bsplit_kernel<<<(3 * 128 * 128 + 255) / 256, 256>>>(Wl, Wr);
    xsplit_kernel<<<(N_NODES * 64 + 255) / 256, 256>>>(x);

    for (int layer = 0; layer < 3; layer++) {
        int cur = layer & 1;          // hin fp16 buffer
        int nxt = cur ^ 1;
        gather_kernel<<<(N_NODES + 7) / 8, 256>>>(ah + cur * (N_NODES * 64));
        sage_mma_kernel<<<GEMM_BLOCKS, 256, SM_TOTAL>>>(
            ah + cur * (N_NODES * 64), al + cur * (N_NODES * 64),
            bhi + layer * 128 * 128, blo + layer * 128 * 128,
            bl + layer * HID, hf32,
            ah + nxt * (N_NODES * 64), al + nxt * (N_NODES * 64),
            (layer < 2) ? 1 : 0, (layer == 2) ? 1 : 0);
    }

    pool_kernel<<<(N_NODES + 127) / 128, 128>>>(hf32, batch);
    bn_kernel<<<1, 128>>>(gamma, beta);
    final_kernel<<<N_GRAPHS, 64>>>(fcW, fcb, out);
}